// round 11
// baseline (speedup 1.0000x reference)
#include <cuda_runtime.h>
#include <cuda_fp16.h>
#include <cstdint>
#include <cstddef>

// ---------------------------------------------------------------------------
// Problem constants
// ---------------------------------------------------------------------------
#define BB_ 4
#define TT_ 4096
#define DD_ 1024
#define MM_ (BB_ * TT_)   // 16384 rows
#define E3_ (3 * DD_)     // 3072

// ---------------------------------------------------------------------------
// Scratch (static device globals -- allocation-free rule)
// ---------------------------------------------------------------------------
__device__ float g_qkv[(size_t)MM_ * E3_];     // k,v written fp32 (cols 1024..3071)
__device__ __half g_qh[(size_t)MM_ * DD_];     // q fp16 (GEMM1 epilogue)
__device__ __half g_xh[(size_t)MM_ * DD_];     // x fp16, reused as A2 fp16
__device__ __half g_wqh[(size_t)E3_ * DD_];
__device__ __half g_woh[(size_t)DD_ * DD_];
__device__ float g_sq[MM_];                    // sum q^2 per row (atomics)
__device__ float g_sk[MM_];                    // sum k^2 per row (atomics)
__device__ float g_invq[MM_];
__device__ float g_kv[BB_ * DD_];
__device__ int   g_mask_is_byte;

// ---------------------------------------------------------------------------
// Helpers (sm_103 baseline ISA: cp.async, ldmatrix, mma.sync)
// ---------------------------------------------------------------------------
__device__ __forceinline__ uint32_t smem_to_u32(const void* smem_ptr) {
    uint32_t addr;
    asm("{ .reg .u64 tmp; cvta.to.shared.u64 tmp, %1; cvt.u32.u64 %0, tmp; }"
        : "=r"(addr) : "l"(smem_ptr));
    return addr;
}

__device__ __forceinline__ void cp16(uint32_t smem_dst, const void* gmem_src) {
    asm volatile("cp.async.cg.shared.global [%0], [%1], 16;\n"
                 :: "r"(smem_dst), "l"(gmem_src));
}
#define CP_ASYNC_COMMIT() asm volatile("cp.async.commit_group;\n" ::: "memory")
#define CP_ASYNC_WAIT_1() asm volatile("cp.async.wait_group 1;\n" ::: "memory")
#define CP_ASYNC_WAIT_0() asm volatile("cp.async.wait_group 0;\n" ::: "memory")

#define LDSM_X4(r0, r1, r2, r3, addr) \
    asm volatile("ldmatrix.sync.aligned.m8n8.x4.shared.b16 {%0,%1,%2,%3}, [%4];" \
                 : "=r"(r0), "=r"(r1), "=r"(r2), "=r"(r3) : "r"(addr))

// fp16 MMA with fp32 accumulate
#define MMA_16816_F16(c, a, b) \
    asm volatile("mma.sync.aligned.m16n8k16.row.col.f32.f16.f16.f32 " \
                 "{%0,%1,%2,%3}, {%4,%5,%6,%7}, {%8,%9}, {%0,%1,%2,%3};" \
                 : "+f"((c)[0]), "+f"((c)[1]), "+f"((c)[2]), "+f"((c)[3]) \
                 : "r"((a)[0]), "r"((a)[1]), "r"((a)[2]), "r"((a)[3]), \
                   "r"((b)[0]), "r"((b)[1]))

#define SMEM_SWIZZLE_128B(byte_offset) \
    ((byte_offset) ^ (((byte_offset) >> 3) & 0x70))

// ---------------------------------------------------------------------------
// fp16 GEMM: CTA tile 128x128, BK=64; 128 thr = 4 warps 2(M)x2(N), warp 64x64.
// Stage: [A 16KB][B 16KB] = 32KB; 3-stage ring = 96KB -> 2 CTAs/SM.
// MODE 0: C = A@B^T + bias -> fp32 out.
// MODE 1 (qkv GEMM): q-tiles (n0<1024) -> fp16 Cq (stride 1024);
//   k/v tiles -> fp32 Ckv (stride 3072); q/k row sumsq fused via atomics.
// ---------------------------------------------------------------------------
#define STAGES 3
#define STAGE_BYTES 32768
#define GS_TOTAL (STAGES * STAGE_BYTES)   // 98304 (2 CTAs -> 192KB/SM)
#define NKT 16                            // 1024 / 64
#define NTHR 128

__device__ __forceinline__ void gemm_issue_load(
    uint32_t sb, int slot, int tid, int m0, int n0, int k0,
    const __half* __restrict__ A, const __half* __restrict__ B)
{
    uint32_t base = sb + slot * STAGE_BYTES;
    #pragma unroll
    for (int i = 0; i < 8; i++) {           // A: 128 rows x 8 chunks = 1024
        int id = tid + (i << 7);
        int r  = id >> 3;
        int cc = id & 7;
        uint32_t soff = SMEM_SWIZZLE_128B((uint32_t)((r << 7) + (cc << 4)));
        cp16(base + soff, A + (size_t)(m0 + r) * DD_ + k0 + (cc << 3));
    }
    #pragma unroll
    for (int i = 0; i < 8; i++) {           // B: 128 rows x 8 chunks = 1024
        int id = tid + (i << 7);
        int r  = id >> 3;
        int cc = id & 7;
        uint32_t soff = SMEM_SWIZZLE_128B((uint32_t)((r << 7) + (cc << 4)));
        cp16(base + 16384 + soff, B + (size_t)(n0 + r) * DD_ + k0 + (cc << 3));
    }
    CP_ASYNC_COMMIT();
}

template <int MODE>
__global__ __launch_bounds__(NTHR, 2) void gemm_f16_kernel(
    const __half* __restrict__ A, const __half* __restrict__ B,
    const float* __restrict__ bias, float* __restrict__ C, int N,
    __half* __restrict__ Cq, float* __restrict__ sq, float* __restrict__ sk)
{
    extern __shared__ char smem[];
    uint32_t sb = smem_to_u32(smem);
    const int tid = threadIdx.x;
    const int wid = tid >> 5;
    const int lane = tid & 31;
    const int n0 = blockIdx.x * 128;   // N fast-varying: wave shares A via L2
    const int m0 = blockIdx.y * 128;
    const int warp_m = (wid & 1) * 64;     // 2 M-groups of 64
    const int warp_n = (wid >> 1) * 64;    // 2 N-groups of 64

    // ldmatrix per-lane address components (validated R2-R10)
    const int lr = lane & 7;
    const int a_row = warp_m + lr + ((lane & 8) ? 8 : 0);
    const int a_ksel = (lane & 16) ? 16 : 0;
    const int b_row = warp_n + lr + ((lane & 16) ? 8 : 0);
    const int b_ksel = (lane & 8) ? 16 : 0;

    float acc[4][8][4];
    #pragma unroll
    for (int i = 0; i < 4; i++)
        #pragma unroll
        for (int j = 0; j < 8; j++)
            #pragma unroll
            for (int k = 0; k < 4; k++) acc[i][j][k] = 0.0f;

    // prologue: stages 0,1
    gemm_issue_load(sb, 0, tid, m0, n0, 0,  A, B);
    gemm_issue_load(sb, 1, tid, m0, n0, 64, A, B);

    int slot = 0;
    for (int it = 0; it < NKT; it++) {
        if (it == NKT - 1) { CP_ASYNC_WAIT_0(); } else { CP_ASYNC_WAIT_1(); }
        __syncthreads();

        int nt = it + 2;
        if (nt < NKT) {
            int ns = slot + 2; if (ns >= STAGES) ns -= STAGES;
            gemm_issue_load(sb, ns, tid, m0, n0, nt << 6, A, B);
        }

        uint32_t ab = sb + slot * STAGE_BYTES;
        uint32_t bb = ab + 16384;

        #pragma unroll
        for (int ks = 0; ks < 4; ks++) {
            uint32_t koff = (uint32_t)(ks << 5);
            uint32_t bfr[8][2];
            #pragma unroll
            for (int nb = 0; nb < 4; nb++) {
                int row = b_row + nb * 16;
                uint32_t addr = bb + (uint32_t)(row << 7)
                              + ((koff + b_ksel) ^ (uint32_t)((row & 7) << 4));
                LDSM_X4(bfr[2 * nb][0], bfr[2 * nb][1],
                        bfr[2 * nb + 1][0], bfr[2 * nb + 1][1], addr);
            }
            uint32_t afr[4][4];
            #pragma unroll
            for (int mf = 0; mf < 4; mf++) {
                int row = a_row + mf * 16;
                uint32_t addr = ab + (uint32_t)(row << 7)
                              + ((koff + a_ksel) ^ (uint32_t)((row & 7) << 4));
                LDSM_X4(afr[mf][0], afr[mf][1], afr[mf][2], afr[mf][3], addr);
            }
            #pragma unroll
            for (int mf = 0; mf < 4; mf++)
                #pragma unroll
                for (int nf = 0; nf < 8; nf++)
                    MMA_16816_F16(acc[mf][nf], afr[mf], bfr[nf]);
        }
        slot++; if (slot >= STAGES) slot = 0;
    }

    // epilogue
    const int gid = lane >> 2;
    const int t4 = lane & 3;
    const int blk = n0 >> 10;   // MODE 1: 0=q, 1=k, 2=v (uniform per CTA)
    #pragma unroll
    for (int mf = 0; mf < 4; mf++) {
        int r0 = m0 + warp_m + mf * 16 + gid;
        float s0 = 0.f, s1 = 0.f;
        #pragma unroll
        for (int nf = 0; nf < 8; nf++) {
            int c = n0 + warp_n + nf * 8 + t4 * 2;
            float2 b2 = *(const float2*)(bias + c);
            float z00 = acc[mf][nf][0] + b2.x;
            float z01 = acc[mf][nf][1] + b2.y;
            float z10 = acc[mf][nf][2] + b2.x;
            float z11 = acc[mf][nf][3] + b2.y;
            if (MODE == 0) {
                *(float2*)(C + (size_t)r0 * N + c) = make_float2(z00, z01);
                *(float2*)(C + (size_t)(r0 + 8) * N + c) = make_float2(z10, z11);
            } else {
                if (blk == 0) {
                    *(__half2*)(Cq + (size_t)r0 * DD_ + c) =
                        __floats2half2_rn(z00, z01);
                    *(__half2*)(Cq + (size_t)(r0 + 8) * DD_ + c) =
                        __floats2half2_rn(z10, z11);
                } else {
                    *(float2*)(C + (size_t)r0 * N + c) = make_float2(z00, z01);
                    *(float2*)(C + (size_t)(r0 + 8) * N + c) = make_float2(z10, z11);
                }
                s0 += z00 * z00 + z01 * z01;
                s1 += z10 * z10 + z11 * z11;
            }
        }
        if (MODE == 1 && blk < 2) {
            // reduce across the 4 t4-lanes sharing this row pair
            s0 += __shfl_xor_sync(0xffffffffu, s0, 1);
            s0 += __shfl_xor_sync(0xffffffffu, s0, 2);
            s1 += __shfl_xor_sync(0xffffffffu, s1, 1);
            s1 += __shfl_xor_sync(0xffffffffu, s1, 2);
            if (t4 == 0) {
                float* dst = (blk == 0) ? sq : sk;
                atomicAdd(dst + r0, s0);
                atomicAdd(dst + r0 + 8, s1);
            }
        }
    }
}

// ---------------------------------------------------------------------------
// Elementwise / reduction kernels
// ---------------------------------------------------------------------------

// fp32 -> fp16 convert, 8 elems/thread
__global__ void cvt_f16_kernel(const float* __restrict__ in,
                               __half* __restrict__ out, int n8)
{
    int idx = blockIdx.x * blockDim.x + threadIdx.x;
    if (idx >= n8) return;
    float4 a = ((const float4*)in)[idx * 2];
    float4 b = ((const float4*)in)[idx * 2 + 1];
    union { uint4 u; __half2 h[4]; } r;
    r.h[0] = __floats2half2_rn(a.x, a.y);
    r.h[1] = __floats2half2_rn(a.z, a.w);
    r.h[2] = __floats2half2_rn(b.x, b.y);
    r.h[3] = __floats2half2_rn(b.z, b.w);
    ((uint4*)out)[idx] = r.u;
}

// zero kv + sumsq buffers (every graph replay)
__global__ void zero_misc_kernel(float* __restrict__ kv,
                                 float* __restrict__ sq, float* __restrict__ sk)
{
    int i = blockIdx.x * blockDim.x + threadIdx.x;
    if (i < BB_ * DD_) kv[i] = 0.0f;
    if (i < MM_) { sq[i] = 0.0f; sk[i] = 0.0f; }
}

__global__ void detect_mask_kernel(const unsigned char* __restrict__ m)
{
    __shared__ int any;
    if (threadIdx.x == 0) any = 0;
    __syncthreads();
    int acc = 0;
    for (int i = threadIdx.x; i < MM_; i += blockDim.x)
        if ((i & 3) != 0) acc |= m[i];
    if (acc) atomicOr(&any, 1);
    __syncthreads();
    if (threadIdx.x == 0) g_mask_is_byte = any ? 1 : 0;
}

// Masked k_hat*v reduction into kv[B,D]; invq from precomputed sumsq.
// Block = 32 rows, 256 threads; thread owns dims [4*tid, 4*tid+4).
__global__ __launch_bounds__(256) void stage2_kernel(
    const float* __restrict__ qkv, const unsigned char* __restrict__ mask,
    const float* __restrict__ sq, const float* __restrict__ sk,
    float* __restrict__ invq, float* __restrict__ kv)
{
    __shared__ float s_ik[32];
    int tid = threadIdx.x;
    int R0 = blockIdx.x * 32;
    int b = R0 >> 12;
    int maskIsByte = g_mask_is_byte;
    const int* mask32 = (const int*)mask;

    if (tid < 32) {
        int row = R0 + tid;
        invq[row] = rsqrtf(sq[row]);
        s_ik[tid] = rsqrtf(sk[row]);
    }
    __syncthreads();

    float ax = 0.f, ay = 0.f, az = 0.f, aw = 0.f;
    for (int r = 0; r < 32; r++) {
        int row = R0 + r;
        bool msk = maskIsByte ? (mask[row] != 0) : (mask32[row] != 0);
        if (!msk) {
            float ik = s_ik[r];
            const float4* base = (const float4*)(qkv + (size_t)row * E3_);
            float4 k4 = base[256 + tid];
            float4 v4 = base[512 + tid];
            ax += k4.x * ik * v4.x;
            ay += k4.y * ik * v4.y;
            az += k4.z * ik * v4.z;
            aw += k4.w * ik * v4.w;
        }
    }
    float* kvb = kv + b * DD_ + tid * 4;
    atomicAdd(kvb + 0, ax);
    atomicAdd(kvb + 1, ay);
    atomicAdd(kvb + 2, az);
    atomicAdd(kvb + 3, aw);
}

// A2 = q(fp16) * invq[row] * kv[b,:] -> fp16. One 128-thread block per row.
__global__ __launch_bounds__(128) void stage3_kernel(
    const __half* __restrict__ qh, const float* __restrict__ invq,
    const float* __restrict__ kv, __half* __restrict__ out)
{
    int tid = threadIdx.x;
    int row = blockIdx.x;
    int b = row >> 12;
    float s = invq[row];
    union { uint4 u; __half2 h[4]; } qv;
    qv.u = *(const uint4*)(qh + (size_t)row * DD_ + tid * 8);
    const float* kp = kv + b * DD_ + tid * 8;
    float4 k0 = *(const float4*)(kp);
    float4 k1 = *(const float4*)(kp + 4);
    float2 q0 = __half22float2(qv.h[0]);
    float2 q1 = __half22float2(qv.h[1]);
    float2 q2 = __half22float2(qv.h[2]);
    float2 q3 = __half22float2(qv.h[3]);
    union { uint4 u; __half2 h[4]; } r;
    r.h[0] = __floats2half2_rn(q0.x * s * k0.x, q0.y * s * k0.y);
    r.h[1] = __floats2half2_rn(q1.x * s * k0.z, q1.y * s * k0.w);
    r.h[2] = __floats2half2_rn(q2.x * s * k1.x, q2.y * s * k1.y);
    r.h[3] = __floats2half2_rn(q3.x * s * k1.z, q3.y * s * k1.w);
    *(uint4*)(out + (size_t)row * DD_ + tid * 8) = r.u;
}

// ---------------------------------------------------------------------------
// Launch
// ---------------------------------------------------------------------------
extern "C" void kernel_launch(void* const* d_in, const int* in_sizes, int n_in,
                              void* d_out, int out_size)
{
    const float* x = (const float*)d_in[0];
    const unsigned char* mask = (const unsigned char*)d_in[1];
    const float* Wqkv = (const float*)d_in[2];
    const float* bqkv = (const float*)d_in[3];
    const float* Wout = (const float*)d_in[4];
    const float* bout = (const float*)d_in[5];
    float* out = (float*)d_out;

    float *p_qkv, *p_invq, *p_kv, *p_sq, *p_sk;
    __half *p_qh, *p_xh, *p_wqh, *p_woh;
    cudaGetSymbolAddress((void**)&p_qkv, g_qkv);
    cudaGetSymbolAddress((void**)&p_invq, g_invq);
    cudaGetSymbolAddress((void**)&p_kv, g_kv);
    cudaGetSymbolAddress((void**)&p_sq, g_sq);
    cudaGetSymbolAddress((void**)&p_sk, g_sk);
    cudaGetSymbolAddress((void**)&p_qh, g_qh);
    cudaGetSymbolAddress((void**)&p_xh, g_xh);
    cudaGetSymbolAddress((void**)&p_wqh, g_wqh);
    cudaGetSymbolAddress((void**)&p_woh, g_woh);

    cudaFuncSetAttribute(gemm_f16_kernel<0>,
                         cudaFuncAttributeMaxDynamicSharedMemorySize, GS_TOTAL);
    cudaFuncSetAttribute(gemm_f16_kernel<1>,
                         cudaFuncAttributeMaxDynamicSharedMemorySize, GS_TOTAL);

    // Launch order keeps GEMM1 at ncu capture slot #4 (-s 5 -c 1).
    zero_misc_kernel<<<MM_ / 256, 256>>>(p_kv, p_sq, p_sk);
    cvt_f16_kernel<<<(MM_ * DD_ / 8 + 255) / 256, 256>>>(x, p_xh, MM_ * DD_ / 8);
    cvt_f16_kernel<<<(E3_ * DD_ / 8 + 255) / 256, 256>>>(Wqkv, p_wqh, E3_ * DD_ / 8);
    // 4: GEMM1: qkv = x @ W_qkv^T + b_qkv; q->fp16, norms fused
    gemm_f16_kernel<1><<<dim3(E3_ / 128, MM_ / 128), NTHR, GS_TOTAL>>>(
        p_xh, p_wqh, bqkv, p_qkv, E3_, p_qh, p_sq, p_sk);
    cvt_f16_kernel<<<(DD_ * DD_ / 8 + 255) / 256, 256>>>(Wout, p_woh, DD_ * DD_ / 8);
    detect_mask_kernel<<<1, 512>>>(mask);
    stage2_kernel<<<MM_ / 32, 256>>>(p_qkv, mask, p_sq, p_sk, p_invq, p_kv);
    // A2 fp16 overwrites x fp16 buffer
    stage3_kernel<<<MM_, 128>>>(p_qh, p_invq, p_kv, p_xh);
    // GEMM2: out = A2 @ W_out^T + b_out
    gemm_f16_kernel<0><<<dim3(DD_ / 128, MM_ / 128), NTHR, GS_TOTAL>>>(
        p_xh, p_woh, bout, out, DD_, (__half*)nullptr, nullptr, nullptr);
}

// round 12
// speedup vs baseline: 1.5020x; 1.5020x over previous
#include <cuda_runtime.h>
#include <cuda_fp16.h>
#include <cstdint>
#include <cstddef>

// ---------------------------------------------------------------------------
// Problem constants
// ---------------------------------------------------------------------------
#define BB_ 4
#define TT_ 4096
#define DD_ 1024
#define MM_ (BB_ * TT_)   // 16384 rows
#define E3_ (3 * DD_)     // 3072

// ---------------------------------------------------------------------------
// Scratch (static device globals -- allocation-free rule)
// ---------------------------------------------------------------------------
__device__ float g_qkv[(size_t)MM_ * E3_];     // k,v written fp32 (cols 1024..3071)
__device__ __half g_qh[(size_t)MM_ * DD_];     // q fp16 (GEMM1 epilogue)
__device__ __half g_xh[(size_t)MM_ * DD_];     // x fp16, reused as A2 fp16
__device__ __half g_wqh[(size_t)E3_ * DD_];
__device__ __half g_woh[(size_t)DD_ * DD_];
__device__ float g_sq[MM_];                    // sum q^2 per row (atomics)
__device__ float g_sk[MM_];                    // sum k^2 per row (atomics)
__device__ float g_invq[MM_];
__device__ float g_kv[BB_ * DD_];
__device__ int   g_mask_is_byte;

// ---------------------------------------------------------------------------
// Helpers (sm_103 baseline ISA: cp.async, ldmatrix, mma.sync)
// ---------------------------------------------------------------------------
__device__ __forceinline__ uint32_t smem_to_u32(const void* smem_ptr) {
    uint32_t addr;
    asm("{ .reg .u64 tmp; cvta.to.shared.u64 tmp, %1; cvt.u32.u64 %0, tmp; }"
        : "=r"(addr) : "l"(smem_ptr));
    return addr;
}

__device__ __forceinline__ void cp16(uint32_t smem_dst, const void* gmem_src) {
    asm volatile("cp.async.cg.shared.global [%0], [%1], 16;\n"
                 :: "r"(smem_dst), "l"(gmem_src));
}
#define CP_ASYNC_COMMIT() asm volatile("cp.async.commit_group;\n" ::: "memory")
#define CP_ASYNC_WAIT_1() asm volatile("cp.async.wait_group 1;\n" ::: "memory")
#define CP_ASYNC_WAIT_0() asm volatile("cp.async.wait_group 0;\n" ::: "memory")

#define LDSM_X4(r0, r1, r2, r3, addr) \
    asm volatile("ldmatrix.sync.aligned.m8n8.x4.shared.b16 {%0,%1,%2,%3}, [%4];" \
                 : "=r"(r0), "=r"(r1), "=r"(r2), "=r"(r3) : "r"(addr))

// fp16 MMA with fp32 accumulate
#define MMA_16816_F16(c, a, b) \
    asm volatile("mma.sync.aligned.m16n8k16.row.col.f32.f16.f16.f32 " \
                 "{%0,%1,%2,%3}, {%4,%5,%6,%7}, {%8,%9}, {%0,%1,%2,%3};" \
                 : "+f"((c)[0]), "+f"((c)[1]), "+f"((c)[2]), "+f"((c)[3]) \
                 : "r"((a)[0]), "r"((a)[1]), "r"((a)[2]), "r"((a)[3]), \
                   "r"((b)[0]), "r"((b)[1]))

#define SMEM_SWIZZLE_128B(byte_offset) \
    ((byte_offset) ^ (((byte_offset) >> 3) & 0x70))

// ---------------------------------------------------------------------------
// fp16 GEMM: CTA tile 128x128, BK=64; 128 thr = 4 warps 2(M)x2(N), warp 64x64.
// Stage: [A 16KB][B 16KB] = 32KB; 3-stage ring = 96KB -> 2 CTAs/SM.
// MODE 0: C = A@B^T + bias -> fp32 out.
// MODE 1 (qkv GEMM): q-tiles (n0<1024) -> fp16 Cq (stride 1024);
//   k/v tiles -> fp32 Ckv (stride 3072); q/k row sumsq fused via atomics.
// ---------------------------------------------------------------------------
#define STAGES 3
#define STAGE_BYTES 32768
#define GS_TOTAL (STAGES * STAGE_BYTES)   // 98304 (2 CTAs -> 192KB/SM)
#define NKT 16                            // 1024 / 64
#define NTHR 128

__device__ __forceinline__ void gemm_issue_load(
    uint32_t sb, int slot, int tid, int m0, int n0, int k0,
    const __half* __restrict__ A, const __half* __restrict__ B)
{
    uint32_t base = sb + slot * STAGE_BYTES;
    #pragma unroll
    for (int i = 0; i < 8; i++) {           // A: 128 rows x 8 chunks = 1024
        int id = tid + (i << 7);
        int r  = id >> 3;
        int cc = id & 7;
        uint32_t soff = SMEM_SWIZZLE_128B((uint32_t)((r << 7) + (cc << 4)));
        cp16(base + soff, A + (size_t)(m0 + r) * DD_ + k0 + (cc << 3));
    }
    #pragma unroll
    for (int i = 0; i < 8; i++) {           // B: 128 rows x 8 chunks = 1024
        int id = tid + (i << 7);
        int r  = id >> 3;
        int cc = id & 7;
        uint32_t soff = SMEM_SWIZZLE_128B((uint32_t)((r << 7) + (cc << 4)));
        cp16(base + 16384 + soff, B + (size_t)(n0 + r) * DD_ + k0 + (cc << 3));
    }
    CP_ASYNC_COMMIT();
}

template <int MODE>
__global__ __launch_bounds__(NTHR, 2) void gemm_f16_kernel(
    const __half* __restrict__ A, const __half* __restrict__ B,
    const float* __restrict__ bias, float* __restrict__ C, int N,
    __half* __restrict__ Cq, float* __restrict__ sq, float* __restrict__ sk)
{
    extern __shared__ char smem[];
    uint32_t sb = smem_to_u32(smem);
    const int tid = threadIdx.x;
    const int wid = tid >> 5;
    const int lane = tid & 31;
    const int n0 = blockIdx.x * 128;   // N fast-varying: wave shares A via L2
    const int m0 = blockIdx.y * 128;
    const int warp_m = (wid & 1) * 64;     // 2 M-groups of 64
    const int warp_n = (wid >> 1) * 64;    // 2 N-groups of 64

    // ldmatrix per-lane address components (validated R2-R10)
    const int lr = lane & 7;
    const int a_row = warp_m + lr + ((lane & 8) ? 8 : 0);
    const int a_ksel = (lane & 16) ? 16 : 0;
    const int b_row = warp_n + lr + ((lane & 16) ? 8 : 0);
    const int b_ksel = (lane & 8) ? 16 : 0;

    float acc[4][8][4];
    #pragma unroll
    for (int i = 0; i < 4; i++)
        #pragma unroll
        for (int j = 0; j < 8; j++)
            #pragma unroll
            for (int k = 0; k < 4; k++) acc[i][j][k] = 0.0f;

    // prologue: stages 0,1
    gemm_issue_load(sb, 0, tid, m0, n0, 0,  A, B);
    gemm_issue_load(sb, 1, tid, m0, n0, 64, A, B);

    int slot = 0;
    for (int it = 0; it < NKT; it++) {
        if (it == NKT - 1) { CP_ASYNC_WAIT_0(); } else { CP_ASYNC_WAIT_1(); }
        __syncthreads();

        int nt = it + 2;
        if (nt < NKT) {
            int ns = slot + 2; if (ns >= STAGES) ns -= STAGES;
            gemm_issue_load(sb, ns, tid, m0, n0, nt << 6, A, B);
        }

        uint32_t ab = sb + slot * STAGE_BYTES;
        uint32_t bb = ab + 16384;

        #pragma unroll
        for (int ks = 0; ks < 4; ks++) {
            uint32_t koff = (uint32_t)(ks << 5);
            uint32_t bfr[8][2];
            #pragma unroll
            for (int nb = 0; nb < 4; nb++) {
                int row = b_row + nb * 16;
                uint32_t addr = bb + (uint32_t)(row << 7)
                              + ((koff + b_ksel) ^ (uint32_t)((row & 7) << 4));
                LDSM_X4(bfr[2 * nb][0], bfr[2 * nb][1],
                        bfr[2 * nb + 1][0], bfr[2 * nb + 1][1], addr);
            }
            uint32_t afr[4][4];
            #pragma unroll
            for (int mf = 0; mf < 4; mf++) {
                int row = a_row + mf * 16;
                uint32_t addr = ab + (uint32_t)(row << 7)
                              + ((koff + a_ksel) ^ (uint32_t)((row & 7) << 4));
                LDSM_X4(afr[mf][0], afr[mf][1], afr[mf][2], afr[mf][3], addr);
            }
            #pragma unroll
            for (int mf = 0; mf < 4; mf++)
                #pragma unroll
                for (int nf = 0; nf < 8; nf++)
                    MMA_16816_F16(acc[mf][nf], afr[mf], bfr[nf]);
        }
        slot++; if (slot >= STAGES) slot = 0;
    }

    // epilogue
    const int gid = lane >> 2;
    const int t4 = lane & 3;
    const int blk = n0 >> 10;   // MODE 1: 0=q, 1=k, 2=v (uniform per CTA)
    #pragma unroll
    for (int mf = 0; mf < 4; mf++) {
        int r0 = m0 + warp_m + mf * 16 + gid;
        float s0 = 0.f, s1 = 0.f;
        #pragma unroll
        for (int nf = 0; nf < 8; nf++) {
            int c = n0 + warp_n + nf * 8 + t4 * 2;
            float2 b2 = *(const float2*)(bias + c);
            float z00 = acc[mf][nf][0] + b2.x;
            float z01 = acc[mf][nf][1] + b2.y;
            float z10 = acc[mf][nf][2] + b2.x;
            float z11 = acc[mf][nf][3] + b2.y;
            if (MODE == 0) {
                *(float2*)(C + (size_t)r0 * N + c) = make_float2(z00, z01);
                *(float2*)(C + (size_t)(r0 + 8) * N + c) = make_float2(z10, z11);
            } else {
                if (blk == 0) {
                    *(__half2*)(Cq + (size_t)r0 * DD_ + c) =
                        __floats2half2_rn(z00, z01);
                    *(__half2*)(Cq + (size_t)(r0 + 8) * DD_ + c) =
                        __floats2half2_rn(z10, z11);
                } else {
                    *(float2*)(C + (size_t)r0 * N + c) = make_float2(z00, z01);
                    *(float2*)(C + (size_t)(r0 + 8) * N + c) = make_float2(z10, z11);
                }
                s0 += z00 * z00 + z01 * z01;
                s1 += z10 * z10 + z11 * z11;
            }
        }
        if (MODE == 1 && blk < 2) {
            // reduce across the 4 t4-lanes sharing this row pair
            s0 += __shfl_xor_sync(0xffffffffu, s0, 1);
            s0 += __shfl_xor_sync(0xffffffffu, s0, 2);
            s1 += __shfl_xor_sync(0xffffffffu, s1, 1);
            s1 += __shfl_xor_sync(0xffffffffu, s1, 2);
            if (t4 == 0) {
                float* dst = (blk == 0) ? sq : sk;
                atomicAdd(dst + r0, s0);
                atomicAdd(dst + r0 + 8, s1);
            }
        }
    }
}

// ---------------------------------------------------------------------------
// Elementwise / reduction kernels
// ---------------------------------------------------------------------------

// fp32 -> fp16 convert, 8 elems/thread
__global__ void cvt_f16_kernel(const float* __restrict__ in,
                               __half* __restrict__ out, int n8)
{
    int idx = blockIdx.x * blockDim.x + threadIdx.x;
    if (idx >= n8) return;
    float4 a = ((const float4*)in)[idx * 2];
    float4 b = ((const float4*)in)[idx * 2 + 1];
    union { uint4 u; __half2 h[4]; } r;
    r.h[0] = __floats2half2_rn(a.x, a.y);
    r.h[1] = __floats2half2_rn(a.z, a.w);
    r.h[2] = __floats2half2_rn(b.x, b.y);
    r.h[3] = __floats2half2_rn(b.z, b.w);
    ((uint4*)out)[idx] = r.u;
}

// zero kv + sumsq buffers (every graph replay)
__global__ void zero_misc_kernel(float* __restrict__ kv,
                                 float* __restrict__ sq, float* __restrict__ sk)
{
    int i = blockIdx.x * blockDim.x + threadIdx.x;
    if (i < BB_ * DD_) kv[i] = 0.0f;
    if (i < MM_) { sq[i] = 0.0f; sk[i] = 0.0f; }
}

__global__ void detect_mask_kernel(const unsigned char* __restrict__ m)
{
    __shared__ int any;
    if (threadIdx.x == 0) any = 0;
    __syncthreads();
    int acc = 0;
    for (int i = threadIdx.x; i < MM_; i += blockDim.x)
        if ((i & 3) != 0) acc |= m[i];
    if (acc) atomicOr(&any, 1);
    __syncthreads();
    if (threadIdx.x == 0) g_mask_is_byte = any ? 1 : 0;
}

// Masked k_hat*v reduction into kv[B,D]; invq from precomputed sumsq.
// Block = 32 rows, 256 threads; thread owns dims [4*tid, 4*tid+4).
__global__ __launch_bounds__(256) void stage2_kernel(
    const float* __restrict__ qkv, const unsigned char* __restrict__ mask,
    const float* __restrict__ sq, const float* __restrict__ sk,
    float* __restrict__ invq, float* __restrict__ kv)
{
    __shared__ float s_ik[32];
    int tid = threadIdx.x;
    int R0 = blockIdx.x * 32;
    int b = R0 >> 12;
    int maskIsByte = g_mask_is_byte;
    const int* mask32 = (const int*)mask;

    if (tid < 32) {
        int row = R0 + tid;
        invq[row] = rsqrtf(sq[row]);
        s_ik[tid] = rsqrtf(sk[row]);
    }
    __syncthreads();

    float ax = 0.f, ay = 0.f, az = 0.f, aw = 0.f;
    for (int r = 0; r < 32; r++) {
        int row = R0 + r;
        bool msk = maskIsByte ? (mask[row] != 0) : (mask32[row] != 0);
        if (!msk) {
            float ik = s_ik[r];
            const float4* base = (const float4*)(qkv + (size_t)row * E3_);
            float4 k4 = base[256 + tid];
            float4 v4 = base[512 + tid];
            ax += k4.x * ik * v4.x;
            ay += k4.y * ik * v4.y;
            az += k4.z * ik * v4.z;
            aw += k4.w * ik * v4.w;
        }
    }
    float* kvb = kv + b * DD_ + tid * 4;
    atomicAdd(kvb + 0, ax);
    atomicAdd(kvb + 1, ay);
    atomicAdd(kvb + 2, az);
    atomicAdd(kvb + 3, aw);
}

// A2 = q(fp16) * invq[row] * kv[b,:] -> fp16. One 128-thread block per row.
__global__ __launch_bounds__(128) void stage3_kernel(
    const __half* __restrict__ qh, const float* __restrict__ invq,
    const float* __restrict__ kv, __half* __restrict__ out)
{
    int tid = threadIdx.x;
    int row = blockIdx.x;
    int b = row >> 12;
    float s = invq[row];
    union { uint4 u; __half2 h[4]; } qv;
    qv.u = *(const uint4*)(qh + (size_t)row * DD_ + tid * 8);
    const float* kp = kv + b * DD_ + tid * 8;
    float4 k0 = *(const float4*)(kp);
    float4 k1 = *(const float4*)(kp + 4);
    float2 q0 = __half22float2(qv.h[0]);
    float2 q1 = __half22float2(qv.h[1]);
    float2 q2 = __half22float2(qv.h[2]);
    float2 q3 = __half22float2(qv.h[3]);
    union { uint4 u; __half2 h[4]; } r;
    r.h[0] = __floats2half2_rn(q0.x * s * k0.x, q0.y * s * k0.y);
    r.h[1] = __floats2half2_rn(q1.x * s * k0.z, q1.y * s * k0.w);
    r.h[2] = __floats2half2_rn(q2.x * s * k1.x, q2.y * s * k1.y);
    r.h[3] = __floats2half2_rn(q3.x * s * k1.z, q3.y * s * k1.w);
    *(uint4*)(out + (size_t)row * DD_ + tid * 8) = r.u;
}

// ---------------------------------------------------------------------------
// Launch
// ---------------------------------------------------------------------------
extern "C" void kernel_launch(void* const* d_in, const int* in_sizes, int n_in,
                              void* d_out, int out_size)
{
    const float* x = (const float*)d_in[0];
    const unsigned char* mask = (const unsigned char*)d_in[1];
    const float* Wqkv = (const float*)d_in[2];
    const float* bqkv = (const float*)d_in[3];
    const float* Wout = (const float*)d_in[4];
    const float* bout = (const float*)d_in[5];
    float* out = (float*)d_out;

    float *p_qkv, *p_invq, *p_kv, *p_sq, *p_sk;
    __half *p_qh, *p_xh, *p_wqh, *p_woh;
    cudaGetSymbolAddress((void**)&p_qkv, g_qkv);
    cudaGetSymbolAddress((void**)&p_invq, g_invq);
    cudaGetSymbolAddress((void**)&p_kv, g_kv);
    cudaGetSymbolAddress((void**)&p_sq, g_sq);
    cudaGetSymbolAddress((void**)&p_sk, g_sk);
    cudaGetSymbolAddress((void**)&p_qh, g_qh);
    cudaGetSymbolAddress((void**)&p_xh, g_xh);
    cudaGetSymbolAddress((void**)&p_wqh, g_wqh);
    cudaGetSymbolAddress((void**)&p_woh, g_woh);

    cudaFuncSetAttribute(gemm_f16_kernel<0>,
                         cudaFuncAttributeMaxDynamicSharedMemorySize, GS_TOTAL);
    cudaFuncSetAttribute(gemm_f16_kernel<1>,
                         cudaFuncAttributeMaxDynamicSharedMemorySize, GS_TOTAL);

    // Launch order keeps GEMM1 at ncu capture slot #4 (-s 5 -c 1).
    zero_misc_kernel<<<MM_ / 256, 256>>>(p_kv, p_sq, p_sk);
    cvt_f16_kernel<<<(MM_ * DD_ / 8 + 255) / 256, 256>>>(x, p_xh, MM_ * DD_ / 8);
    cvt_f16_kernel<<<(E3_ * DD_ / 8 + 255) / 256, 256>>>(Wqkv, p_wqh, E3_ * DD_ / 8);
    // 4: GEMM1: qkv = x @ W_qkv^T + b_qkv; q->fp16, norms fused
    gemm_f16_kernel<1><<<dim3(E3_ / 128, MM_ / 128), NTHR, GS_TOTAL>>>(
        p_xh, p_wqh, bqkv, p_qkv, E3_, p_qh, p_sq, p_sk);
    cvt_f16_kernel<<<(DD_ * DD_ / 8 + 255) / 256, 256>>>(Wout, p_woh, DD_ * DD_ / 8);
    detect_mask_kernel<<<1, 512>>>(mask);
    stage2_kernel<<<MM_ / 32, 256>>>(p_qkv, mask, p_sq, p_sk, p_invq, p_kv);
    // A2 fp16 overwrites x fp16 buffer
    stage3_kernel<<<MM_, 128>>>(p_qh, p_invq, p_kv, p_xh);
    // GEMM2: out = A2 @ W_out^T + b_out
    gemm_f16_kernel<0><<<dim3(DD_ / 128, MM_ / 128), NTHR, GS_TOTAL>>>(
        p_xh, p_woh, bout, out, DD_, (__half*)nullptr, nullptr, nullptr);
}

// round 13
// speedup vs baseline: 1.5226x; 1.0137x over previous
#include <cuda_runtime.h>
#include <cuda_fp16.h>
#include <cstdint>
#include <cstddef>

// ---------------------------------------------------------------------------
// Problem constants
// ---------------------------------------------------------------------------
#define BB_ 4
#define TT_ 4096
#define DD_ 1024
#define MM_ (BB_ * TT_)   // 16384 rows
#define E3_ (3 * DD_)     // 3072

// ---------------------------------------------------------------------------
// Scratch (static device globals -- allocation-free rule)
// ---------------------------------------------------------------------------
__device__ __half g_qh[(size_t)MM_ * DD_];     // q fp16 (GEMM1 epilogue)
__device__ __half g_kh[(size_t)MM_ * DD_];     // k fp16
__device__ __half g_vh[(size_t)MM_ * DD_];     // v fp16
__device__ __half g_xh[(size_t)MM_ * DD_];     // x fp16, reused as A2 fp16
__device__ __half g_wqh[(size_t)E3_ * DD_];
__device__ __half g_woh[(size_t)DD_ * DD_];
__device__ float g_sq[MM_];                    // sum q^2 per row (atomics)
__device__ float g_sk[MM_];                    // sum k^2 per row (atomics)
__device__ float g_invq[MM_];
__device__ float g_kv[BB_ * DD_];
__device__ int   g_mask_is_byte;

// ---------------------------------------------------------------------------
// Helpers (sm_103 baseline ISA: cp.async, ldmatrix, mma.sync)
// ---------------------------------------------------------------------------
__device__ __forceinline__ uint32_t smem_to_u32(const void* smem_ptr) {
    uint32_t addr;
    asm("{ .reg .u64 tmp; cvta.to.shared.u64 tmp, %1; cvt.u32.u64 %0, tmp; }"
        : "=r"(addr) : "l"(smem_ptr));
    return addr;
}

__device__ __forceinline__ void cp16(uint32_t smem_dst, const void* gmem_src) {
    asm volatile("cp.async.cg.shared.global [%0], [%1], 16;\n"
                 :: "r"(smem_dst), "l"(gmem_src));
}
#define CP_ASYNC_COMMIT() asm volatile("cp.async.commit_group;\n" ::: "memory")
#define CP_ASYNC_WAIT_1() asm volatile("cp.async.wait_group 1;\n" ::: "memory")
#define CP_ASYNC_WAIT_0() asm volatile("cp.async.wait_group 0;\n" ::: "memory")

#define LDSM_X4(r0, r1, r2, r3, addr) \
    asm volatile("ldmatrix.sync.aligned.m8n8.x4.shared.b16 {%0,%1,%2,%3}, [%4];" \
                 : "=r"(r0), "=r"(r1), "=r"(r2), "=r"(r3) : "r"(addr))

// fp16 MMA with fp32 accumulate
#define MMA_16816_F16(c, a, b) \
    asm volatile("mma.sync.aligned.m16n8k16.row.col.f32.f16.f16.f32 " \
                 "{%0,%1,%2,%3}, {%4,%5,%6,%7}, {%8,%9}, {%0,%1,%2,%3};" \
                 : "+f"((c)[0]), "+f"((c)[1]), "+f"((c)[2]), "+f"((c)[3]) \
                 : "r"((a)[0]), "r"((a)[1]), "r"((a)[2]), "r"((a)[3]), \
                   "r"((b)[0]), "r"((b)[1]))

#define SMEM_SWIZZLE_128B(byte_offset) \
    ((byte_offset) ^ (((byte_offset) >> 3) & 0x70))

// ---------------------------------------------------------------------------
// fp16 GEMM: CTA tile 128x128, BK=64; 128 thr = 4 warps 2(M)x2(N), warp 64x64.
// Stage: [A 16KB][B 16KB] = 32KB; 3-stage ring = 96KB -> 2 CTAs/SM.
// MODE 0: C = A@B^T + bias -> fp32 out (stride N).
// MODE 1 (qkv GEMM): q/k/v tiles -> fp16 buffers (stride 1024 each);
//   q/k row sumsq fused via atomics.
// ---------------------------------------------------------------------------
#define STAGES 3
#define STAGE_BYTES 32768
#define GS_TOTAL (STAGES * STAGE_BYTES)   // 98304 (2 CTAs -> 192KB/SM)
#define NKT 16                            // 1024 / 64
#define NTHR 128

__device__ __forceinline__ void gemm_issue_load(
    uint32_t sb, int slot, int tid, int m0, int n0, int k0,
    const __half* __restrict__ A, const __half* __restrict__ B)
{
    uint32_t base = sb + slot * STAGE_BYTES;
    #pragma unroll
    for (int i = 0; i < 8; i++) {           // A: 128 rows x 8 chunks = 1024
        int id = tid + (i << 7);
        int r  = id >> 3;
        int cc = id & 7;
        uint32_t soff = SMEM_SWIZZLE_128B((uint32_t)((r << 7) + (cc << 4)));
        cp16(base + soff, A + (size_t)(m0 + r) * DD_ + k0 + (cc << 3));
    }
    #pragma unroll
    for (int i = 0; i < 8; i++) {           // B: 128 rows x 8 chunks = 1024
        int id = tid + (i << 7);
        int r  = id >> 3;
        int cc = id & 7;
        uint32_t soff = SMEM_SWIZZLE_128B((uint32_t)((r << 7) + (cc << 4)));
        cp16(base + 16384 + soff, B + (size_t)(n0 + r) * DD_ + k0 + (cc << 3));
    }
    CP_ASYNC_COMMIT();
}

template <int MODE>
__global__ __launch_bounds__(NTHR, 2) void gemm_f16_kernel(
    const __half* __restrict__ A, const __half* __restrict__ B,
    const float* __restrict__ bias, float* __restrict__ C, int N,
    __half* __restrict__ Cq, __half* __restrict__ Ck, __half* __restrict__ Cv,
    float* __restrict__ sq, float* __restrict__ sk)
{
    extern __shared__ char smem[];
    uint32_t sb = smem_to_u32(smem);
    const int tid = threadIdx.x;
    const int wid = tid >> 5;
    const int lane = tid & 31;
    const int n0 = blockIdx.x * 128;   // N fast-varying: wave shares A via L2
    const int m0 = blockIdx.y * 128;
    const int warp_m = (wid & 1) * 64;     // 2 M-groups of 64
    const int warp_n = (wid >> 1) * 64;    // 2 N-groups of 64

    // ldmatrix per-lane address components (validated R2-R12)
    const int lr = lane & 7;
    const int a_row = warp_m + lr + ((lane & 8) ? 8 : 0);
    const int a_ksel = (lane & 16) ? 16 : 0;
    const int b_row = warp_n + lr + ((lane & 16) ? 8 : 0);
    const int b_ksel = (lane & 8) ? 16 : 0;

    float acc[4][8][4];
    #pragma unroll
    for (int i = 0; i < 4; i++)
        #pragma unroll
        for (int j = 0; j < 8; j++)
            #pragma unroll
            for (int k = 0; k < 4; k++) acc[i][j][k] = 0.0f;

    // prologue: stages 0,1
    gemm_issue_load(sb, 0, tid, m0, n0, 0,  A, B);
    gemm_issue_load(sb, 1, tid, m0, n0, 64, A, B);

    int slot = 0;
    for (int it = 0; it < NKT; it++) {
        if (it == NKT - 1) { CP_ASYNC_WAIT_0(); } else { CP_ASYNC_WAIT_1(); }
        __syncthreads();

        int nt = it + 2;
        if (nt < NKT) {
            int ns = slot + 2; if (ns >= STAGES) ns -= STAGES;
            gemm_issue_load(sb, ns, tid, m0, n0, nt << 6, A, B);
        }

        uint32_t ab = sb + slot * STAGE_BYTES;
        uint32_t bb = ab + 16384;

        #pragma unroll
        for (int ks = 0; ks < 4; ks++) {
            uint32_t koff = (uint32_t)(ks << 5);
            uint32_t bfr[8][2];
            #pragma unroll
            for (int nb = 0; nb < 4; nb++) {
                int row = b_row + nb * 16;
                uint32_t addr = bb + (uint32_t)(row << 7)
                              + ((koff + b_ksel) ^ (uint32_t)((row & 7) << 4));
                LDSM_X4(bfr[2 * nb][0], bfr[2 * nb][1],
                        bfr[2 * nb + 1][0], bfr[2 * nb + 1][1], addr);
            }
            uint32_t afr[4][4];
            #pragma unroll
            for (int mf = 0; mf < 4; mf++) {
                int row = a_row + mf * 16;
                uint32_t addr = ab + (uint32_t)(row << 7)
                              + ((koff + a_ksel) ^ (uint32_t)((row & 7) << 4));
                LDSM_X4(afr[mf][0], afr[mf][1], afr[mf][2], afr[mf][3], addr);
            }
            #pragma unroll
            for (int mf = 0; mf < 4; mf++)
                #pragma unroll
                for (int nf = 0; nf < 8; nf++)
                    MMA_16816_F16(acc[mf][nf], afr[mf], bfr[nf]);
        }
        slot++; if (slot >= STAGES) slot = 0;
    }

    // epilogue
    const int gid = lane >> 2;
    const int t4 = lane & 3;
    const int blk = n0 >> 10;            // MODE 1: 0=q, 1=k, 2=v (uniform per CTA)
    const int ncl = n0 & 1023;           // column base within q/k/v buffer
    __half* __restrict__ H = (MODE == 1)
        ? ((blk == 0) ? Cq : (blk == 1) ? Ck : Cv) : (__half*)nullptr;
    #pragma unroll
    for (int mf = 0; mf < 4; mf++) {
        int r0 = m0 + warp_m + mf * 16 + gid;
        float s0 = 0.f, s1 = 0.f;
        #pragma unroll
        for (int nf = 0; nf < 8; nf++) {
            int c = n0 + warp_n + nf * 8 + t4 * 2;
            float2 b2 = *(const float2*)(bias + c);
            float z00 = acc[mf][nf][0] + b2.x;
            float z01 = acc[mf][nf][1] + b2.y;
            float z10 = acc[mf][nf][2] + b2.x;
            float z11 = acc[mf][nf][3] + b2.y;
            if (MODE == 0) {
                *(float2*)(C + (size_t)r0 * N + c) = make_float2(z00, z01);
                *(float2*)(C + (size_t)(r0 + 8) * N + c) = make_float2(z10, z11);
            } else {
                int cl = ncl + warp_n + nf * 8 + t4 * 2;
                *(__half2*)(H + (size_t)r0 * DD_ + cl) = __floats2half2_rn(z00, z01);
                *(__half2*)(H + (size_t)(r0 + 8) * DD_ + cl) = __floats2half2_rn(z10, z11);
                s0 += z00 * z00 + z01 * z01;
                s1 += z10 * z10 + z11 * z11;
            }
        }
        if (MODE == 1 && blk < 2) {
            // reduce across the 4 t4-lanes sharing this row pair
            s0 += __shfl_xor_sync(0xffffffffu, s0, 1);
            s0 += __shfl_xor_sync(0xffffffffu, s0, 2);
            s1 += __shfl_xor_sync(0xffffffffu, s1, 1);
            s1 += __shfl_xor_sync(0xffffffffu, s1, 2);
            if (t4 == 0) {
                float* dst = (blk == 0) ? sq : sk;
                atomicAdd(dst + r0, s0);
                atomicAdd(dst + r0 + 8, s1);
            }
        }
    }
}

// ---------------------------------------------------------------------------
// Elementwise / reduction kernels
// ---------------------------------------------------------------------------

// fp32 -> fp16 convert, 8 elems/thread
__global__ void cvt_f16_kernel(const float* __restrict__ in,
                               __half* __restrict__ out, int n8)
{
    int idx = blockIdx.x * blockDim.x + threadIdx.x;
    if (idx >= n8) return;
    float4 a = ((const float4*)in)[idx * 2];
    float4 b = ((const float4*)in)[idx * 2 + 1];
    union { uint4 u; __half2 h[4]; } r;
    r.h[0] = __floats2half2_rn(a.x, a.y);
    r.h[1] = __floats2half2_rn(a.z, a.w);
    r.h[2] = __floats2half2_rn(b.x, b.y);
    r.h[3] = __floats2half2_rn(b.z, b.w);
    ((uint4*)out)[idx] = r.u;
}

// zero kv + sumsq buffers (every graph replay)
__global__ void zero_misc_kernel(float* __restrict__ kv,
                                 float* __restrict__ sq, float* __restrict__ sk)
{
    int i = blockIdx.x * blockDim.x + threadIdx.x;
    if (i < BB_ * DD_) kv[i] = 0.0f;
    if (i < MM_) { sq[i] = 0.0f; sk[i] = 0.0f; }
}

__global__ void detect_mask_kernel(const unsigned char* __restrict__ m)
{
    __shared__ int any;
    if (threadIdx.x == 0) any = 0;
    __syncthreads();
    int acc = 0;
    for (int i = threadIdx.x; i < MM_; i += blockDim.x)
        if ((i & 3) != 0) acc |= m[i];
    if (acc) atomicOr(&any, 1);
    __syncthreads();
    if (threadIdx.x == 0) g_mask_is_byte = any ? 1 : 0;
}

// Masked k_hat*v reduction into kv[B,D]; invq from precomputed sumsq.
// Block = 32 rows, 256 threads; thread owns dims [4*tid, 4*tid+4).
__global__ __launch_bounds__(256) void stage2_kernel(
    const __half* __restrict__ kh, const __half* __restrict__ vh,
    const unsigned char* __restrict__ mask,
    const float* __restrict__ sq, const float* __restrict__ sk,
    float* __restrict__ invq, float* __restrict__ kv)
{
    __shared__ float s_ik[32];
    int tid = threadIdx.x;
    int R0 = blockIdx.x * 32;
    int b = R0 >> 12;
    int maskIsByte = g_mask_is_byte;
    const int* mask32 = (const int*)mask;

    if (tid < 32) {
        int row = R0 + tid;
        invq[row] = rsqrtf(sq[row]);
        s_ik[tid] = rsqrtf(sk[row]);
    }
    __syncthreads();

    float ax = 0.f, ay = 0.f, az = 0.f, aw = 0.f;
    for (int r = 0; r < 32; r++) {
        int row = R0 + r;
        bool msk = maskIsByte ? (mask[row] != 0) : (mask32[row] != 0);
        if (!msk) {
            float ik = s_ik[r];
            union { uint2 u; __half2 h[2]; } kk, vv;
            kk.u = *(const uint2*)(kh + (size_t)row * DD_ + tid * 4);
            vv.u = *(const uint2*)(vh + (size_t)row * DD_ + tid * 4);
            float2 k0 = __half22float2(kk.h[0]);
            float2 k1 = __half22float2(kk.h[1]);
            float2 v0 = __half22float2(vv.h[0]);
            float2 v1 = __half22float2(vv.h[1]);
            ax += k0.x * ik * v0.x;
            ay += k0.y * ik * v0.y;
            az += k1.x * ik * v1.x;
            aw += k1.y * ik * v1.y;
        }
    }
    float* kvb = kv + b * DD_ + tid * 4;
    atomicAdd(kvb + 0, ax);
    atomicAdd(kvb + 1, ay);
    atomicAdd(kvb + 2, az);
    atomicAdd(kvb + 3, aw);
}

// A2 = q(fp16) * invq[row] * kv[b,:] -> fp16. One 128-thread block per row.
__global__ __launch_bounds__(128) void stage3_kernel(
    const __half* __restrict__ qh, const float* __restrict__ invq,
    const float* __restrict__ kv, __half* __restrict__ out)
{
    int tid = threadIdx.x;
    int row = blockIdx.x;
    int b = row >> 12;
    float s = invq[row];
    union { uint4 u; __half2 h[4]; } qv;
    qv.u = *(const uint4*)(qh + (size_t)row * DD_ + tid * 8);
    const float* kp = kv + b * DD_ + tid * 8;
    float4 k0 = *(const float4*)(kp);
    float4 k1 = *(const float4*)(kp + 4);
    float2 q0 = __half22float2(qv.h[0]);
    float2 q1 = __half22float2(qv.h[1]);
    float2 q2 = __half22float2(qv.h[2]);
    float2 q3 = __half22float2(qv.h[3]);
    union { uint4 u; __half2 h[4]; } r;
    r.h[0] = __floats2half2_rn(q0.x * s * k0.x, q0.y * s * k0.y);
    r.h[1] = __floats2half2_rn(q1.x * s * k0.z, q1.y * s * k0.w);
    r.h[2] = __floats2half2_rn(q2.x * s * k1.x, q2.y * s * k1.y);
    r.h[3] = __floats2half2_rn(q3.x * s * k1.z, q3.y * s * k1.w);
    *(uint4*)(out + (size_t)row * DD_ + tid * 8) = r.u;
}

// ---------------------------------------------------------------------------
// Launch
// ---------------------------------------------------------------------------
extern "C" void kernel_launch(void* const* d_in, const int* in_sizes, int n_in,
                              void* d_out, int out_size)
{
    const float* x = (const float*)d_in[0];
    const unsigned char* mask = (const unsigned char*)d_in[1];
    const float* Wqkv = (const float*)d_in[2];
    const float* bqkv = (const float*)d_in[3];
    const float* Wout = (const float*)d_in[4];
    const float* bout = (const float*)d_in[5];
    float* out = (float*)d_out;

    float *p_invq, *p_kv, *p_sq, *p_sk;
    __half *p_qh, *p_kh, *p_vh, *p_xh, *p_wqh, *p_woh;
    cudaGetSymbolAddress((void**)&p_invq, g_invq);
    cudaGetSymbolAddress((void**)&p_kv, g_kv);
    cudaGetSymbolAddress((void**)&p_sq, g_sq);
    cudaGetSymbolAddress((void**)&p_sk, g_sk);
    cudaGetSymbolAddress((void**)&p_qh, g_qh);
    cudaGetSymbolAddress((void**)&p_kh, g_kh);
    cudaGetSymbolAddress((void**)&p_vh, g_vh);
    cudaGetSymbolAddress((void**)&p_xh, g_xh);
    cudaGetSymbolAddress((void**)&p_wqh, g_wqh);
    cudaGetSymbolAddress((void**)&p_woh, g_woh);

    cudaFuncSetAttribute(gemm_f16_kernel<0>,
                         cudaFuncAttributeMaxDynamicSharedMemorySize, GS_TOTAL);
    cudaFuncSetAttribute(gemm_f16_kernel<1>,
                         cudaFuncAttributeMaxDynamicSharedMemorySize, GS_TOTAL);

    // Launch order keeps GEMM1 at ncu capture slot #4 (-s 5 -c 1).
    zero_misc_kernel<<<MM_ / 256, 256>>>(p_kv, p_sq, p_sk);
    cvt_f16_kernel<<<(MM_ * DD_ / 8 + 255) / 256, 256>>>(x, p_xh, MM_ * DD_ / 8);
    cvt_f16_kernel<<<(E3_ * DD_ / 8 + 255) / 256, 256>>>(Wqkv, p_wqh, E3_ * DD_ / 8);
    // 4: GEMM1: qkv = x @ W_qkv^T + b_qkv; q/k/v -> fp16, norms fused
    gemm_f16_kernel<1><<<dim3(E3_ / 128, MM_ / 128), NTHR, GS_TOTAL>>>(
        p_xh, p_wqh, bqkv, (float*)nullptr, E3_, p_qh, p_kh, p_vh, p_sq, p_sk);
    cvt_f16_kernel<<<(DD_ * DD_ / 8 + 255) / 256, 256>>>(Wout, p_woh, DD_ * DD_ / 8);
    detect_mask_kernel<<<1, 512>>>(mask);
    stage2_kernel<<<MM_ / 32, 256>>>(p_kh, p_vh, mask, p_sq, p_sk, p_invq, p_kv);
    // A2 fp16 overwrites x fp16 buffer
    stage3_kernel<<<MM_, 128>>>(p_qh, p_invq, p_kv, p_xh);
    // GEMM2: out = A2 @ W_out^T + b_out
    gemm_f16_kernel<0><<<dim3(DD_ / 128, MM_ / 128), NTHR, GS_TOTAL>>>(
        p_xh, p_woh, bout, out, DD_, (__half*)nullptr, (__half*)nullptr,
        (__half*)nullptr, nullptr, nullptr);
}

// round 14
// speedup vs baseline: 1.5503x; 1.0182x over previous
#include <cuda_runtime.h>
#include <cuda_fp16.h>
#include <cstdint>
#include <cstddef>

// ---------------------------------------------------------------------------
// Problem constants
// ---------------------------------------------------------------------------
#define BB_ 4
#define TT_ 4096
#define DD_ 1024
#define MM_ (BB_ * TT_)   // 16384 rows
#define E3_ (3 * DD_)     // 3072

// ---------------------------------------------------------------------------
// Scratch (static device globals -- allocation-free rule)
// ---------------------------------------------------------------------------
__device__ __half g_qh[(size_t)MM_ * DD_];     // q fp16 (GEMM1 epilogue)
__device__ __half g_kh[(size_t)MM_ * DD_];     // k fp16
__device__ __half g_vh[(size_t)MM_ * DD_];     // v fp16
__device__ __half g_xh[(size_t)MM_ * DD_];     // x fp16
__device__ __half g_wqh[(size_t)E3_ * DD_];
__device__ __half g_woh[(size_t)DD_ * DD_];
__device__ __half g_wp[(size_t)BB_ * DD_ * DD_];  // per-batch Wout*kv fp16
__device__ float g_sq[MM_];                    // sum q^2 per row (atomics)
__device__ float g_sk[MM_];                    // sum k^2 per row (atomics)
__device__ float g_invq[MM_];
__device__ float g_kv[BB_ * DD_];
__device__ int   g_mask_is_byte;

// ---------------------------------------------------------------------------
// Helpers (sm_103 baseline ISA: cp.async, ldmatrix, mma.sync)
// ---------------------------------------------------------------------------
__device__ __forceinline__ uint32_t smem_to_u32(const void* smem_ptr) {
    uint32_t addr;
    asm("{ .reg .u64 tmp; cvta.to.shared.u64 tmp, %1; cvt.u32.u64 %0, tmp; }"
        : "=r"(addr) : "l"(smem_ptr));
    return addr;
}

__device__ __forceinline__ void cp16(uint32_t smem_dst, const void* gmem_src) {
    asm volatile("cp.async.cg.shared.global [%0], [%1], 16;\n"
                 :: "r"(smem_dst), "l"(gmem_src));
}
#define CP_ASYNC_COMMIT() asm volatile("cp.async.commit_group;\n" ::: "memory")
#define CP_ASYNC_WAIT_1() asm volatile("cp.async.wait_group 1;\n" ::: "memory")
#define CP_ASYNC_WAIT_0() asm volatile("cp.async.wait_group 0;\n" ::: "memory")

#define LDSM_X4(r0, r1, r2, r3, addr) \
    asm volatile("ldmatrix.sync.aligned.m8n8.x4.shared.b16 {%0,%1,%2,%3}, [%4];" \
                 : "=r"(r0), "=r"(r1), "=r"(r2), "=r"(r3) : "r"(addr))

// fp16 MMA with fp32 accumulate
#define MMA_16816_F16(c, a, b) \
    asm volatile("mma.sync.aligned.m16n8k16.row.col.f32.f16.f16.f32 " \
                 "{%0,%1,%2,%3}, {%4,%5,%6,%7}, {%8,%9}, {%0,%1,%2,%3};" \
                 : "+f"((c)[0]), "+f"((c)[1]), "+f"((c)[2]), "+f"((c)[3]) \
                 : "r"((a)[0]), "r"((a)[1]), "r"((a)[2]), "r"((a)[3]), \
                   "r"((b)[0]), "r"((b)[1]))

#define SMEM_SWIZZLE_128B(byte_offset) \
    ((byte_offset) ^ (((byte_offset) >> 3) & 0x70))

// ---------------------------------------------------------------------------
// fp16 GEMM: CTA tile 128x128, BK=64; 128 thr = 4 warps 2(M)x2(N), warp 64x64.
// Stage: [A 16KB][B 16KB] = 32KB; 3-stage ring = 96KB -> 2 CTAs/SM.
// MODE 1 (qkv GEMM): q/k/v tiles -> fp16 buffers (stride 1024 each);
//   q/k row sumsq fused via atomics.
// MODE 2 (out GEMM): B is per-batch Wp (offset m0>>12 * 1MB elems);
//   C = invq[r] * (A @ B^T) + bias -> fp32.
// ---------------------------------------------------------------------------
#define STAGES 3
#define STAGE_BYTES 32768
#define GS_TOTAL (STAGES * STAGE_BYTES)   // 98304 (2 CTAs -> 192KB/SM)
#define NKT 16                            // 1024 / 64
#define NTHR 128

__device__ __forceinline__ void gemm_issue_load(
    uint32_t sb, int slot, int tid, int m0, int n0, int k0,
    const __half* __restrict__ A, const __half* __restrict__ B)
{
    uint32_t base = sb + slot * STAGE_BYTES;
    #pragma unroll
    for (int i = 0; i < 8; i++) {           // A: 128 rows x 8 chunks = 1024
        int id = tid + (i << 7);
        int r  = id >> 3;
        int cc = id & 7;
        uint32_t soff = SMEM_SWIZZLE_128B((uint32_t)((r << 7) + (cc << 4)));
        cp16(base + soff, A + (size_t)(m0 + r) * DD_ + k0 + (cc << 3));
    }
    #pragma unroll
    for (int i = 0; i < 8; i++) {           // B: 128 rows x 8 chunks = 1024
        int id = tid + (i << 7);
        int r  = id >> 3;
        int cc = id & 7;
        uint32_t soff = SMEM_SWIZZLE_128B((uint32_t)((r << 7) + (cc << 4)));
        cp16(base + 16384 + soff, B + (size_t)(n0 + r) * DD_ + k0 + (cc << 3));
    }
    CP_ASYNC_COMMIT();
}

template <int MODE>
__global__ __launch_bounds__(NTHR, 2) void gemm_f16_kernel(
    const __half* __restrict__ A, const __half* __restrict__ B,
    const float* __restrict__ bias, float* __restrict__ C, int N,
    __half* __restrict__ Cq, __half* __restrict__ Ck, __half* __restrict__ Cv,
    float* __restrict__ sq, float* __restrict__ sk)
{
    extern __shared__ char smem[];
    uint32_t sb = smem_to_u32(smem);
    const int tid = threadIdx.x;
    const int wid = tid >> 5;
    const int lane = tid & 31;
    const int n0 = blockIdx.x * 128;   // N fast-varying: wave shares A via L2
    const int m0 = blockIdx.y * 128;
    const int warp_m = (wid & 1) * 64;     // 2 M-groups of 64
    const int warp_n = (wid >> 1) * 64;    // 2 N-groups of 64

    // MODE 2: per-batch B (Wout * kv[batch]) selected by row block
    const __half* __restrict__ Bp = (MODE == 2)
        ? B + ((size_t)(m0 >> 12) << 20) : B;

    // ldmatrix per-lane address components (validated R2-R13)
    const int lr = lane & 7;
    const int a_row = warp_m + lr + ((lane & 8) ? 8 : 0);
    const int a_ksel = (lane & 16) ? 16 : 0;
    const int b_row = warp_n + lr + ((lane & 16) ? 8 : 0);
    const int b_ksel = (lane & 8) ? 16 : 0;

    float acc[4][8][4];
    #pragma unroll
    for (int i = 0; i < 4; i++)
        #pragma unroll
        for (int j = 0; j < 8; j++)
            #pragma unroll
            for (int k = 0; k < 4; k++) acc[i][j][k] = 0.0f;

    // prologue: stages 0,1
    gemm_issue_load(sb, 0, tid, m0, n0, 0,  A, Bp);
    gemm_issue_load(sb, 1, tid, m0, n0, 64, A, Bp);

    int slot = 0;
    for (int it = 0; it < NKT; it++) {
        if (it == NKT - 1) { CP_ASYNC_WAIT_0(); } else { CP_ASYNC_WAIT_1(); }
        __syncthreads();

        int nt = it + 2;
        if (nt < NKT) {
            int ns = slot + 2; if (ns >= STAGES) ns -= STAGES;
            gemm_issue_load(sb, ns, tid, m0, n0, nt << 6, A, Bp);
        }

        uint32_t ab = sb + slot * STAGE_BYTES;
        uint32_t bb = ab + 16384;

        #pragma unroll
        for (int ks = 0; ks < 4; ks++) {
            uint32_t koff = (uint32_t)(ks << 5);
            uint32_t bfr[8][2];
            #pragma unroll
            for (int nb = 0; nb < 4; nb++) {
                int row = b_row + nb * 16;
                uint32_t addr = bb + (uint32_t)(row << 7)
                              + ((koff + b_ksel) ^ (uint32_t)((row & 7) << 4));
                LDSM_X4(bfr[2 * nb][0], bfr[2 * nb][1],
                        bfr[2 * nb + 1][0], bfr[2 * nb + 1][1], addr);
            }
            uint32_t afr[4][4];
            #pragma unroll
            for (int mf = 0; mf < 4; mf++) {
                int row = a_row + mf * 16;
                uint32_t addr = ab + (uint32_t)(row << 7)
                              + ((koff + a_ksel) ^ (uint32_t)((row & 7) << 4));
                LDSM_X4(afr[mf][0], afr[mf][1], afr[mf][2], afr[mf][3], addr);
            }
            #pragma unroll
            for (int mf = 0; mf < 4; mf++)
                #pragma unroll
                for (int nf = 0; nf < 8; nf++)
                    MMA_16816_F16(acc[mf][nf], afr[mf], bfr[nf]);
        }
        slot++; if (slot >= STAGES) slot = 0;
    }

    // epilogue
    const int gid = lane >> 2;
    const int t4 = lane & 3;
    const int blk = n0 >> 10;            // MODE 1: 0=q, 1=k, 2=v (uniform per CTA)
    const int ncl = n0 & 1023;           // column base within q/k/v buffer
    __half* __restrict__ H = (MODE == 1)
        ? ((blk == 0) ? Cq : (blk == 1) ? Ck : Cv) : (__half*)nullptr;
    #pragma unroll
    for (int mf = 0; mf < 4; mf++) {
        int r0 = m0 + warp_m + mf * 16 + gid;
        float iq0 = 1.f, iq1 = 1.f;
        if (MODE == 2) { iq0 = sq[r0]; iq1 = sq[r0 + 8]; }   // sq carries invq
        float s0 = 0.f, s1 = 0.f;
        #pragma unroll
        for (int nf = 0; nf < 8; nf++) {
            int c = n0 + warp_n + nf * 8 + t4 * 2;
            float2 b2 = *(const float2*)(bias + c);
            if (MODE == 2) {
                float z00 = acc[mf][nf][0] * iq0 + b2.x;
                float z01 = acc[mf][nf][1] * iq0 + b2.y;
                float z10 = acc[mf][nf][2] * iq1 + b2.x;
                float z11 = acc[mf][nf][3] * iq1 + b2.y;
                *(float2*)(C + (size_t)r0 * N + c) = make_float2(z00, z01);
                *(float2*)(C + (size_t)(r0 + 8) * N + c) = make_float2(z10, z11);
            } else {
                float z00 = acc[mf][nf][0] + b2.x;
                float z01 = acc[mf][nf][1] + b2.y;
                float z10 = acc[mf][nf][2] + b2.x;
                float z11 = acc[mf][nf][3] + b2.y;
                int cl = ncl + warp_n + nf * 8 + t4 * 2;
                *(__half2*)(H + (size_t)r0 * DD_ + cl) = __floats2half2_rn(z00, z01);
                *(__half2*)(H + (size_t)(r0 + 8) * DD_ + cl) = __floats2half2_rn(z10, z11);
                s0 += z00 * z00 + z01 * z01;
                s1 += z10 * z10 + z11 * z11;
            }
        }
        if (MODE == 1 && blk < 2) {
            // reduce across the 4 t4-lanes sharing this row pair
            s0 += __shfl_xor_sync(0xffffffffu, s0, 1);
            s0 += __shfl_xor_sync(0xffffffffu, s0, 2);
            s1 += __shfl_xor_sync(0xffffffffu, s1, 1);
            s1 += __shfl_xor_sync(0xffffffffu, s1, 2);
            if (t4 == 0) {
                float* dst = (blk == 0) ? sq : sk;
                atomicAdd(dst + r0, s0);
                atomicAdd(dst + r0 + 8, s1);
            }
        }
    }
}

// ---------------------------------------------------------------------------
// Elementwise / reduction kernels
// ---------------------------------------------------------------------------

// fp32 -> fp16 convert, 8 elems/thread
__global__ void cvt_f16_kernel(const float* __restrict__ in,
                               __half* __restrict__ out, int n8)
{
    int idx = blockIdx.x * blockDim.x + threadIdx.x;
    if (idx >= n8) return;
    float4 a = ((const float4*)in)[idx * 2];
    float4 b = ((const float4*)in)[idx * 2 + 1];
    union { uint4 u; __half2 h[4]; } r;
    r.h[0] = __floats2half2_rn(a.x, a.y);
    r.h[1] = __floats2half2_rn(a.z, a.w);
    r.h[2] = __floats2half2_rn(b.x, b.y);
    r.h[3] = __floats2half2_rn(b.z, b.w);
    ((uint4*)out)[idx] = r.u;
}

// zero kv + sumsq buffers (every graph replay)
__global__ void zero_misc_kernel(float* __restrict__ kv,
                                 float* __restrict__ sq, float* __restrict__ sk)
{
    int i = blockIdx.x * blockDim.x + threadIdx.x;
    if (i < BB_ * DD_) kv[i] = 0.0f;
    if (i < MM_) { sq[i] = 0.0f; sk[i] = 0.0f; }
}

__global__ void detect_mask_kernel(const unsigned char* __restrict__ m)
{
    __shared__ int any;
    if (threadIdx.x == 0) any = 0;
    __syncthreads();
    int acc = 0;
    for (int i = threadIdx.x; i < MM_; i += blockDim.x)
        if ((i & 3) != 0) acc |= m[i];
    if (acc) atomicOr(&any, 1);
    __syncthreads();
    if (threadIdx.x == 0) g_mask_is_byte = any ? 1 : 0;
}

// Masked k_hat*v reduction into kv[B,D]; invq from precomputed sumsq.
// Block = 32 rows, 256 threads; thread owns dims [4*tid, 4*tid+4).
__global__ __launch_bounds__(256) void stage2_kernel(
    const __half* __restrict__ kh, const __half* __restrict__ vh,
    const unsigned char* __restrict__ mask,
    const float* __restrict__ sq, const float* __restrict__ sk,
    float* __restrict__ invq, float* __restrict__ kv)
{
    __shared__ float s_ik[32];
    int tid = threadIdx.x;
    int R0 = blockIdx.x * 32;
    int b = R0 >> 12;
    int maskIsByte = g_mask_is_byte;
    const int* mask32 = (const int*)mask;

    if (tid < 32) {
        int row = R0 + tid;
        invq[row] = rsqrtf(sq[row]);
        s_ik[tid] = rsqrtf(sk[row]);
    }
    __syncthreads();

    float ax = 0.f, ay = 0.f, az = 0.f, aw = 0.f;
    for (int r = 0; r < 32; r++) {
        int row = R0 + r;
        bool msk = maskIsByte ? (mask[row] != 0) : (mask32[row] != 0);
        if (!msk) {
            float ik = s_ik[r];
            union { uint2 u; __half2 h[2]; } kk, vv;
            kk.u = *(const uint2*)(kh + (size_t)row * DD_ + tid * 4);
            vv.u = *(const uint2*)(vh + (size_t)row * DD_ + tid * 4);
            float2 k0 = __half22float2(kk.h[0]);
            float2 k1 = __half22float2(kk.h[1]);
            float2 v0 = __half22float2(vv.h[0]);
            float2 v1 = __half22float2(vv.h[1]);
            ax += k0.x * ik * v0.x;
            ay += k0.y * ik * v0.y;
            az += k1.x * ik * v1.x;
            aw += k1.y * ik * v1.y;
        }
    }
    float* kvb = kv + b * DD_ + tid * 4;
    atomicAdd(kvb + 0, ax);
    atomicAdd(kvb + 1, ay);
    atomicAdd(kvb + 2, az);
    atomicAdd(kvb + 3, aw);
}

// Wp[b][n][c] = Wout[n][c] * kv[b][c]  -> fp16. 8 elems/thread.
__global__ __launch_bounds__(256) void build_wp_kernel(
    const __half* __restrict__ woh, const float* __restrict__ kv,
    __half* __restrict__ wp)
{
    int idx = blockIdx.x * blockDim.x + threadIdx.x;   // 8-elem chunk id
    int b = idx >> 17;                // (1024*1024/8) = 131072 chunks per batch
    int off = idx & 131071;
    int c = (off & 127) * 8;          // column within row
    union { uint4 u; __half2 h[4]; } w;
    w.u = *(const uint4*)(woh + (size_t)off * 8);
    const float* kp = kv + b * DD_ + c;
    float4 k0 = *(const float4*)(kp);
    float4 k1 = *(const float4*)(kp + 4);
    float2 w0 = __half22float2(w.h[0]);
    float2 w1 = __half22float2(w.h[1]);
    float2 w2 = __half22float2(w.h[2]);
    float2 w3 = __half22float2(w.h[3]);
    union { uint4 u; __half2 h[4]; } r;
    r.h[0] = __floats2half2_rn(w0.x * k0.x, w0.y * k0.y);
    r.h[1] = __floats2half2_rn(w1.x * k0.z, w1.y * k0.w);
    r.h[2] = __floats2half2_rn(w2.x * k1.x, w2.y * k1.y);
    r.h[3] = __floats2half2_rn(w3.x * k1.z, w3.y * k1.w);
    *(uint4*)(wp + (size_t)idx * 8) = r.u;
}

// ---------------------------------------------------------------------------
// Launch
// ---------------------------------------------------------------------------
extern "C" void kernel_launch(void* const* d_in, const int* in_sizes, int n_in,
                              void* d_out, int out_size)
{
    const float* x = (const float*)d_in[0];
    const unsigned char* mask = (const unsigned char*)d_in[1];
    const float* Wqkv = (const float*)d_in[2];
    const float* bqkv = (const float*)d_in[3];
    const float* Wout = (const float*)d_in[4];
    const float* bout = (const float*)d_in[5];
    float* out = (float*)d_out;

    float *p_invq, *p_kv, *p_sq, *p_sk;
    __half *p_qh, *p_kh, *p_vh, *p_xh, *p_wqh, *p_woh, *p_wp;
    cudaGetSymbolAddress((void**)&p_invq, g_invq);
    cudaGetSymbolAddress((void**)&p_kv, g_kv);
    cudaGetSymbolAddress((void**)&p_sq, g_sq);
    cudaGetSymbolAddress((void**)&p_sk, g_sk);
    cudaGetSymbolAddress((void**)&p_qh, g_qh);
    cudaGetSymbolAddress((void**)&p_kh, g_kh);
    cudaGetSymbolAddress((void**)&p_vh, g_vh);
    cudaGetSymbolAddress((void**)&p_xh, g_xh);
    cudaGetSymbolAddress((void**)&p_wqh, g_wqh);
    cudaGetSymbolAddress((void**)&p_woh, g_woh);
    cudaGetSymbolAddress((void**)&p_wp, g_wp);

    cudaFuncSetAttribute(gemm_f16_kernel<1>,
                         cudaFuncAttributeMaxDynamicSharedMemorySize, GS_TOTAL);
    cudaFuncSetAttribute(gemm_f16_kernel<2>,
                         cudaFuncAttributeMaxDynamicSharedMemorySize, GS_TOTAL);

    // Launch order keeps GEMM1 at ncu capture slot #4 (-s 5 -c 1).
    zero_misc_kernel<<<MM_ / 256, 256>>>(p_kv, p_sq, p_sk);
    cvt_f16_kernel<<<(MM_ * DD_ / 8 + 255) / 256, 256>>>(x, p_xh, MM_ * DD_ / 8);
    cvt_f16_kernel<<<(E3_ * DD_ / 8 + 255) / 256, 256>>>(Wqkv, p_wqh, E3_ * DD_ / 8);
    // 4: GEMM1: qkv = x @ W_qkv^T + b_qkv; q/k/v -> fp16, norms fused
    gemm_f16_kernel<1><<<dim3(E3_ / 128, MM_ / 128), NTHR, GS_TOTAL>>>(
        p_xh, p_wqh, bqkv, (float*)nullptr, E3_, p_qh, p_kh, p_vh, p_sq, p_sk);
    cvt_f16_kernel<<<(DD_ * DD_ / 8 + 255) / 256, 256>>>(Wout, p_woh, DD_ * DD_ / 8);
    detect_mask_kernel<<<1, 512>>>(mask);
    stage2_kernel<<<MM_ / 32, 256>>>(p_kh, p_vh, mask, p_sq, p_sk, p_invq, p_kv);
    // Wp[b] = Wout * kv[b]
    build_wp_kernel<<<BB_ * DD_ * DD_ / 8 / 256, 256>>>(p_woh, p_kv, p_wp);
    // GEMM2: out = invq * (q @ Wp_b^T) + b_out
    gemm_f16_kernel<2><<<dim3(DD_ / 128, MM_ / 128), NTHR, GS_TOTAL>>>(
        p_qh, p_wp, bout, out, DD_, (__half*)nullptr, (__half*)nullptr,
        (__half*)nullptr, p_invq, nullptr);
}